// round 7
// baseline (speedup 1.0000x reference)
#include <cuda_runtime.h>
#include <cuda_fp16.h>
#include <cstdint>

// ============================================================
// WeightOnlyInt8Linear: out = input @ weight^T * scales
// R7: fp16 m16n8k16 GEMM, occ-2, with B kept as int8 in smem and
// converted int8->fp16 in registers (exact; bias trick: 5 ALU ops
// per fragment). Cuts smem crossbar traffic per ktile/CTA from
// 128KB to 104KB (< tensor-pipe time) and halves B L2 traffic.
//   CTA 128x128x64, 3-stage cp.async (24KB/stage), 256 thr,
//   warp 64x32, 2 CTA/SM.
// A: fp16 fragment-major (one LDS.128/frag). B: int8 frag-major
// (one LDS.32/frag: bytes {k=2t,2t+1,2t+8,2t+9} of col g).
// ============================================================

static constexpr int MDIM = 8192;
static constexpr int NDIM = 4096;
static constexpr int KDIM = 4096;

static constexpr int BM = 128;
static constexpr int BN = 128;
static constexpr int BK = 64;             // 4 k16 steps
static constexpr int STAGES = 3;
static constexpr int NKT = KDIM / BK;     // 64

static constexpr int A_ST_BYTES = (BM / 16) * (BK / 16) * 512;   // 16384
static constexpr int B_ST_BYTES = (BN / 8) * (BK / 16) * 128;    // 8192 (int8)
static constexpr int STAGE_BYTES = A_ST_BYTES + B_ST_BYTES;      // 24576
static constexpr int SMEM_BYTES = STAGES * STAGE_BYTES;          // 73728

// static scratch
__device__ __half  g_af[(size_t)MDIM * KDIM];  // 64 MB fp16 frag-major [m16][k16][512B]
__device__ int8_t  g_wq[(size_t)NDIM * KDIM];  // 16 MB int8 frag-major [n8][k16][128B]

// ---------------- helpers ----------------
__device__ __forceinline__ uint32_t smem_u32(const void* p) {
    uint32_t a;
    asm("{ .reg .u64 t; cvta.to.shared.u64 t, %1; cvt.u32.u64 %0, t; }"
        : "=r"(a) : "l"(p));
    return a;
}
__device__ __forceinline__ void cp_async16(uint32_t dst, const void* src) {
    asm volatile("cp.async.cg.shared.global [%0], [%1], 16;"
                 :: "r"(dst), "l"(src) : "memory");
}
#define CP_COMMIT() asm volatile("cp.async.commit_group;" ::: "memory")
#define CP_WAIT(n)  asm volatile("cp.async.wait_group %0;" :: "n"(n) : "memory")

#define MMA_F16(d, a0, a1, a2, a3, b0, b1)                                    \
    asm volatile("mma.sync.aligned.m16n8k16.row.col.f32.f16.f16.f32 "         \
                 "{%0,%1,%2,%3}, {%4,%5,%6,%7}, {%8,%9}, {%0,%1,%2,%3};"      \
                 : "+f"((d)[0]), "+f"((d)[1]), "+f"((d)[2]), "+f"((d)[3])     \
                 : "r"(a0), "r"(a1), "r"(a2), "r"(a3), "r"(b0), "r"(b1))

// int8x4 -> 2x half2 (exact). q = packed bytes {x0,x1,x2,x3} (int8).
// lo = halves(x0,x1), hi = halves(x2,x3).
__device__ __forceinline__ void cvt_s8x4_f16x4(uint32_t q, uint32_t& lo, uint32_t& hi) {
    uint32_t b = q ^ 0x80808080u;            // bias to unsigned
    uint32_t l, h;
    asm("prmt.b32 %0, %1, %2, 0x4140;" : "=r"(l) : "r"(b), "r"(0x64646464u));
    asm("prmt.b32 %0, %1, %2, 0x4342;" : "=r"(h) : "r"(b), "r"(0x64646464u));
    asm("sub.f16x2 %0, %1, %2;" : "=r"(lo) : "r"(l), "r"(0x64806480u)); // -1152
    asm("sub.f16x2 %0, %1, %2;" : "=r"(hi) : "r"(h), "r"(0x64806480u));
}

// ---------------- A pack: f32 -> f16 fragment-major ----------------
__global__ void __launch_bounds__(256) pack_a_kernel(const float* __restrict__ a) {
    const int rt = blockIdx.y;
    const int k0 = blockIdx.x * 512;
    __shared__ __half sh[16][520];

    #pragma unroll
    for (int u = threadIdx.x; u < 2048; u += 256) {
        const int row = u >> 7, c4 = u & 127;
        float4 v = *reinterpret_cast<const float4*>(
            a + (size_t)(rt * 16 + row) * KDIM + k0 + c4 * 4);
        __half2* d = reinterpret_cast<__half2*>(&sh[row][c4 * 4]);
        d[0] = __floats2half2_rn(v.x, v.y);
        d[1] = __floats2half2_rn(v.z, v.w);
    }
    __syncthreads();

    #pragma unroll
    for (int w = threadIdx.x; w < 1024; w += 256) {
        const int kt = w >> 5, lane = w & 31;
        const int g = lane >> 2, t = lane & 3;
        const int kc = kt * 16 + 2 * t;
        uint32_t r0 = *reinterpret_cast<const uint32_t*>(&sh[g][kc]);
        uint32_t r1 = *reinterpret_cast<const uint32_t*>(&sh[g + 8][kc]);
        uint32_t r2 = *reinterpret_cast<const uint32_t*>(&sh[g][kc + 8]);
        uint32_t r3 = *reinterpret_cast<const uint32_t*>(&sh[g + 8][kc + 8]);
        int4* dst = reinterpret_cast<int4*>(
            reinterpret_cast<char*>(g_af)
            + (((size_t)rt * 256 + (k0 >> 4) + kt) << 9) + lane * 16);
        *dst = make_int4(r0, r1, r2, r3);
    }
}

// ---------------- W pack: int32 -> int8 fragment-major ----------------
// frag word (lane): bytes { w[kc], w[kc+1], w[kc+8], w[kc+9] } of col g,
// kc = kt*16 + 2t. 128B per n8 x k16 tile.
__global__ void __launch_bounds__(256) pack_w_kernel(const int* __restrict__ w) {
    const int nt = blockIdx.y;          // 8-col tile
    const int k0 = blockIdx.x * 512;
    __shared__ int8_t sh[8][520];

    #pragma unroll
    for (int u = threadIdx.x; u < 1024; u += 256) {   // 8 cols * 128 int4
        const int row = u >> 7, c4 = u & 127;
        int4 v = *reinterpret_cast<const int4*>(
            w + (size_t)(nt * 8 + row) * KDIM + k0 + c4 * 4);
        sh[row][c4 * 4 + 0] = (int8_t)v.x;
        sh[row][c4 * 4 + 1] = (int8_t)v.y;
        sh[row][c4 * 4 + 2] = (int8_t)v.z;
        sh[row][c4 * 4 + 3] = (int8_t)v.w;
    }
    __syncthreads();

    #pragma unroll
    for (int u = threadIdx.x; u < 1024; u += 256) {   // 32 k16-tiles * 32 lanes
        const int kt = u >> 5, lane = u & 31;
        const int g = lane >> 2, t = lane & 3;
        const int kc = kt * 16 + 2 * t;
        uint32_t word =
              (uint32_t)(uint8_t)sh[g][kc]
            | ((uint32_t)(uint8_t)sh[g][kc + 1] << 8)
            | ((uint32_t)(uint8_t)sh[g][kc + 8] << 16)
            | ((uint32_t)(uint8_t)sh[g][kc + 9] << 24);
        *reinterpret_cast<uint32_t*>(
            g_wq + (((size_t)nt * 256 + (k0 >> 4) + kt) << 7) + lane * 4) = word;
    }
}

// ---------------- main GEMM ----------------
__global__ void __launch_bounds__(256, 2) gemm_kernel(
    const float* __restrict__ scales, float* __restrict__ out)
{
    extern __shared__ char smem[];
    const uint32_t sbase = smem_u32(smem);

    const int tid  = threadIdx.x;
    const int lane = tid & 31;
    const int wid  = tid >> 5;        // 0..7
    const int wm   = wid >> 2;        // 0..1 (64-row slab)
    const int wn   = wid & 3;         // 0..3 (32-col slab)
    const int g    = lane >> 2;
    const int t    = lane & 3;

    // grouped-M raster
    const int num_n  = NDIM / BN;     // 32
    const int GROUPM = 8;
    const int bid = blockIdx.x;
    const int grp = bid / (GROUPM * num_n);
    const int rem = bid % (GROUPM * num_n);
    const int m0 = (grp * GROUPM + (rem % GROUPM)) * BM;
    const int n0 = (rem / GROUPM) * BN;
    const int rt0 = m0 >> 4;
    const int nt0 = n0 >> 3;

    float acc[4][4][4];
    #pragma unroll
    for (int i = 0; i < 4; i++)
        #pragma unroll
        for (int j = 0; j < 4; j++)
            #pragma unroll
            for (int c = 0; c < 4; c++) acc[i][j][c] = 0.0f;

    const char* gA = reinterpret_cast<const char*>(g_af);
    const char* gB = reinterpret_cast<const char*>(g_wq);

    // A stage: [mi(8)][ks(4)][512B]; B stage: [nj(16)][ks(4)][128B]
    #define ISSUE_STAGE(kt_, slot_)                                            \
    do {                                                                       \
        const int _kt4 = (kt_) * 4;                                            \
        const uint32_t _sa = sbase + (uint32_t)(slot_) * STAGE_BYTES;          \
        const uint32_t _sb = _sa + A_ST_BYTES;                                 \
        _Pragma("unroll")                                                      \
        for (int u = tid; u < 1024; u += 256) {        /* A: 16KB */           \
            const int mi = u >> 7;                                             \
            cp_async16(_sa + (u << 4),                                         \
                gA + (((size_t)(rt0 + mi) * 256 + _kt4) << 9)                  \
                   + ((u & 127) << 4));                                        \
        }                                                                      \
        _Pragma("unroll")                                                      \
        for (int u = tid; u < 512; u += 256) {         /* B: 8KB */            \
            const int nj = u >> 5;                                             \
            cp_async16(_sb + (u << 4),                                         \
                gB + (((size_t)(nt0 + nj) * 256 + _kt4) << 7)                  \
                   + ((u & 31) << 4));                                         \
        }                                                                      \
    } while (0)

    ISSUE_STAGE(0, 0); CP_COMMIT();
    ISSUE_STAGE(1, 1); CP_COMMIT();

    int s_cur = 0, s_nxt = 2;
    const uint32_t lane16 = (uint32_t)lane * 16;
    const uint32_t lane4  = (uint32_t)lane * 4;

    for (int kt = 0; kt < NKT; kt++) {
        CP_WAIT(1);
        __syncthreads();

        const int kn = kt + 2;
        if (kn < NKT) ISSUE_STAGE(kn, s_nxt);
        CP_COMMIT();

        const uint32_t sa = sbase + (uint32_t)s_cur * STAGE_BYTES;
        const uint32_t sb = sa + A_ST_BYTES;

        #pragma unroll
        for (int ks = 0; ks < 4; ks++) {
            uint32_t bf[4][2];
            #pragma unroll
            for (int j = 0; j < 4; j++) {
                uint32_t q;
                const uint32_t addr =
                    sb + (uint32_t)(((wn * 4 + j) * 4 + ks) * 128) + lane4;
                asm volatile("ld.shared.u32 %0, [%1];" : "=r"(q) : "r"(addr));
                cvt_s8x4_f16x4(q, bf[j][0], bf[j][1]);
            }
            #pragma unroll
            for (int i = 0; i < 4; i++) {
                uint32_t a0, a1, a2, a3;
                const uint32_t addr =
                    sa + (uint32_t)(((wm * 4 + i) * 4 + ks) * 512) + lane16;
                asm volatile("ld.shared.v4.u32 {%0,%1,%2,%3}, [%4];"
                             : "=r"(a0), "=r"(a1), "=r"(a2), "=r"(a3) : "r"(addr));
                #pragma unroll
                for (int j = 0; j < 4; j++)
                    MMA_F16(acc[i][j], a0, a1, a2, a3, bf[j][0], bf[j][1]);
            }
        }

        s_cur = (s_cur == 2) ? 0 : s_cur + 1;
        s_nxt = (s_nxt == 2) ? 0 : s_nxt + 1;
    }

    // ---- epilogue: scale and store ----
    const int orow0 = m0 + wm * 64;
    const int ocol0 = n0 + wn * 32;
    #pragma unroll
    for (int j = 0; j < 4; j++) {
        const int col = ocol0 + j * 8 + 2 * t;
        const float2 sc = *reinterpret_cast<const float2*>(scales + col);
        #pragma unroll
        for (int i = 0; i < 4; i++) {
            const int row = orow0 + i * 16 + g;
            float2 v0 = { acc[i][j][0] * sc.x, acc[i][j][1] * sc.y };
            float2 v1 = { acc[i][j][2] * sc.x, acc[i][j][3] * sc.y };
            *reinterpret_cast<float2*>(out + (size_t)row * NDIM + col)       = v0;
            *reinterpret_cast<float2*>(out + (size_t)(row + 8) * NDIM + col) = v1;
        }
    }
}

// ---------------- host ----------------
extern "C" void kernel_launch(void* const* d_in, const int* in_sizes, int n_in,
                              void* d_out, int out_size) {
    const float* input  = (const float*)d_in[0];
    const int*   weight = (const int*)d_in[1];
    const float* scales = (const float*)d_in[2];
    float* out = (float*)d_out;

    {
        dim3 ga(KDIM / 512, MDIM / 16);   // (8, 512)
        pack_a_kernel<<<ga, 256>>>(input);
        dim3 gw(KDIM / 512, NDIM / 8);    // (8, 512)
        pack_w_kernel<<<gw, 256>>>(weight);
    }

    cudaFuncSetAttribute(gemm_kernel,
                         cudaFuncAttributeMaxDynamicSharedMemorySize, SMEM_BYTES);
    const int grid = (MDIM / BM) * (NDIM / BN);   // 2048
    gemm_kernel<<<grid, 256, SMEM_BYTES>>>(scales, out);
}

// round 8
// speedup vs baseline: 1.0224x; 1.0224x over previous
#include <cuda_runtime.h>
#include <cuda_fp16.h>
#include <cstdint>

// ============================================================
// WeightOnlyInt8Linear: out = input @ weight^T * scales
// R8: R6 config (fp16 m16n8k16, CTA 128x128x64, 3-stage cp.async,
// 256 thr, warp 64x32, 2 CTA/SM) + explicit register-level
// software pipeline of fragment loads: while MMAs for (ks,i)
// run, loads for (ks,i+1) / (ks+1, B-set + first A) are in
// flight in a second register buffer. Targets the LDS->MMA
// dependency bubbles behind the measured 11 cyc/mma (rt=8).
// ============================================================

static constexpr int MDIM = 8192;
static constexpr int NDIM = 4096;
static constexpr int KDIM = 4096;

static constexpr int BM = 128;
static constexpr int BN = 128;
static constexpr int BK = 64;             // 4 k16 steps
static constexpr int STAGES = 3;
static constexpr int NKT = KDIM / BK;     // 64

static constexpr int A_ST_BYTES = (BM / 16) * (BK / 16) * 512;   // 16384
static constexpr int B_ST_BYTES = (BN / 8) * (BK / 16) * 256;    // 16384
static constexpr int STAGE_BYTES = A_ST_BYTES + B_ST_BYTES;      // 32768
static constexpr int SMEM_BYTES = STAGES * STAGE_BYTES;          // 98304

// static scratch: fragment-major fp16
__device__ __half g_af[(size_t)MDIM * KDIM];   // 64 MB: [m16-tile][k16-tile][512B]
__device__ __half g_wf[(size_t)NDIM * KDIM];   // 32 MB: [n8-tile][k16-tile][256B]

// ---------------- helpers ----------------
__device__ __forceinline__ uint32_t smem_u32(const void* p) {
    uint32_t a;
    asm("{ .reg .u64 t; cvta.to.shared.u64 t, %1; cvt.u32.u64 %0, t; }"
        : "=r"(a) : "l"(p));
    return a;
}
__device__ __forceinline__ void cp_async16(uint32_t dst, const void* src) {
    asm volatile("cp.async.cg.shared.global [%0], [%1], 16;"
                 :: "r"(dst), "l"(src) : "memory");
}
#define CP_COMMIT() asm volatile("cp.async.commit_group;" ::: "memory")
#define CP_WAIT(n)  asm volatile("cp.async.wait_group %0;" :: "n"(n) : "memory")

#define MMA_F16(d, a0, a1, a2, a3, b0, b1)                                    \
    asm volatile("mma.sync.aligned.m16n8k16.row.col.f32.f16.f16.f32 "         \
                 "{%0,%1,%2,%3}, {%4,%5,%6,%7}, {%8,%9}, {%0,%1,%2,%3};"      \
                 : "+f"((d)[0]), "+f"((d)[1]), "+f"((d)[2]), "+f"((d)[3])     \
                 : "r"(a0), "r"(a1), "r"(a2), "r"(a3), "r"(b0), "r"(b1))

// ---------------- A pack: f32 -> f16 fragment-major ----------------
__global__ void __launch_bounds__(256) pack_a_kernel(const float* __restrict__ a) {
    const int rt = blockIdx.y;
    const int k0 = blockIdx.x * 512;
    __shared__ __half sh[16][520];

    #pragma unroll
    for (int u = threadIdx.x; u < 2048; u += 256) {
        const int row = u >> 7, c4 = u & 127;
        float4 v = *reinterpret_cast<const float4*>(
            a + (size_t)(rt * 16 + row) * KDIM + k0 + c4 * 4);
        __half2* d = reinterpret_cast<__half2*>(&sh[row][c4 * 4]);
        d[0] = __floats2half2_rn(v.x, v.y);
        d[1] = __floats2half2_rn(v.z, v.w);
    }
    __syncthreads();

    #pragma unroll
    for (int w = threadIdx.x; w < 1024; w += 256) {
        const int kt = w >> 5, lane = w & 31;
        const int g = lane >> 2, t = lane & 3;
        const int kc = kt * 16 + 2 * t;
        uint32_t r0 = *reinterpret_cast<const uint32_t*>(&sh[g][kc]);
        uint32_t r1 = *reinterpret_cast<const uint32_t*>(&sh[g + 8][kc]);
        uint32_t r2 = *reinterpret_cast<const uint32_t*>(&sh[g][kc + 8]);
        uint32_t r3 = *reinterpret_cast<const uint32_t*>(&sh[g + 8][kc + 8]);
        int4* dst = reinterpret_cast<int4*>(
            reinterpret_cast<char*>(g_af)
            + (((size_t)rt * 256 + (k0 >> 4) + kt) << 9) + lane * 16);
        *dst = make_int4(r0, r1, r2, r3);
    }
}

// ---------------- W pack: int32 -> f16 fragment-major ----------------
__global__ void __launch_bounds__(256) pack_w_kernel(const int* __restrict__ w) {
    const int nt = blockIdx.y;
    const int k0 = blockIdx.x * 512;
    __shared__ __half sh[8][520];

    #pragma unroll
    for (int u = threadIdx.x; u < 1024; u += 256) {
        const int row = u >> 7, c4 = u & 127;
        int4 v = *reinterpret_cast<const int4*>(
            w + (size_t)(nt * 8 + row) * KDIM + k0 + c4 * 4);
        __half2* d = reinterpret_cast<__half2*>(&sh[row][c4 * 4]);
        d[0] = __floats2half2_rn((float)v.x, (float)v.y);
        d[1] = __floats2half2_rn((float)v.z, (float)v.w);
    }
    __syncthreads();

    #pragma unroll
    for (int u2 = threadIdx.x; u2 < 1024; u2 += 256) {
        const int kt = u2 >> 5, lane = u2 & 31;
        const int g = lane >> 2, t = lane & 3;
        const int kc = kt * 16 + 2 * t;
        uint32_t b0 = *reinterpret_cast<const uint32_t*>(&sh[g][kc]);
        uint32_t b1 = *reinterpret_cast<const uint32_t*>(&sh[g][kc + 8]);
        int2* dst = reinterpret_cast<int2*>(
            reinterpret_cast<char*>(g_wf)
            + (((size_t)nt * 256 + (k0 >> 4) + kt) << 8) + lane * 8);
        *dst = make_int2(b0, b1);
    }
}

// ---------------- main GEMM ----------------
__global__ void __launch_bounds__(256, 2) gemm_kernel(
    const float* __restrict__ scales, float* __restrict__ out)
{
    extern __shared__ char smem[];
    const uint32_t sbase = smem_u32(smem);

    const int tid  = threadIdx.x;
    const int lane = tid & 31;
    const int wid  = tid >> 5;        // 0..7
    const int wm   = wid >> 2;        // 0..1 (64-row slab)
    const int wn   = wid & 3;         // 0..3 (32-col slab)
    const int g    = lane >> 2;
    const int t    = lane & 3;

    // grouped-M raster
    const int num_n  = NDIM / BN;     // 32
    const int GROUPM = 8;
    const int bid = blockIdx.x;
    const int grp = bid / (GROUPM * num_n);
    const int rem = bid % (GROUPM * num_n);
    const int m0 = (grp * GROUPM + (rem % GROUPM)) * BM;
    const int n0 = (rem / GROUPM) * BN;
    const int rt0 = m0 >> 4;
    const int nt0 = n0 >> 3;

    float acc[4][4][4];
    #pragma unroll
    for (int i = 0; i < 4; i++)
        #pragma unroll
        for (int j = 0; j < 4; j++)
            #pragma unroll
            for (int c = 0; c < 4; c++) acc[i][j][c] = 0.0f;

    const char* gA = reinterpret_cast<const char*>(g_af);
    const char* gB = reinterpret_cast<const char*>(g_wf);

    #define ISSUE_STAGE(kt_, slot_)                                            \
    do {                                                                       \
        const int _kt4 = (kt_) * 4;                                            \
        const uint32_t _sa = sbase + (uint32_t)(slot_) * STAGE_BYTES;          \
        const uint32_t _sb = _sa + A_ST_BYTES;                                 \
        _Pragma("unroll")                                                      \
        for (int u = tid; u < 1024; u += 256) {        /* A: 16KB */           \
            const int mi = u >> 7;                                             \
            cp_async16(_sa + (u << 4),                                         \
                gA + (((size_t)(rt0 + mi) * 256 + _kt4) << 9)                  \
                   + ((u & 127) << 4));                                        \
        }                                                                      \
        _Pragma("unroll")                                                      \
        for (int u = tid; u < 1024; u += 256) {        /* B: 16KB */           \
            const int nj = u >> 6;                                             \
            cp_async16(_sb + (u << 4),                                         \
                gB + (((size_t)(nt0 + nj) * 256 + _kt4) << 8)                  \
                   + ((u & 63) << 4));                                         \
        }                                                                      \
    } while (0)

    ISSUE_STAGE(0, 0); CP_COMMIT();
    ISSUE_STAGE(1, 1); CP_COMMIT();

    int s_cur = 0, s_nxt = 2;
    const uint32_t lane16 = (uint32_t)lane * 16;
    const uint32_t lane8  = (uint32_t)lane * 8;
    const uint32_t a_warp = (uint32_t)(wm * 4) * 2048;   // (wm*4+i)*4*512 base
    const uint32_t b_warp = (uint32_t)(wn * 4) * 1024;   // (wn*4+j)*4*256 base

    // register double buffers
    uint32_t bf[2][4][2];   // B set for one ks (4 frags)
    uint32_t af[2][4];      // one A frag

    #define LD_B(sb_, ks_, buf_)                                               \
    do {                                                                       \
        _Pragma("unroll")                                                      \
        for (int j = 0; j < 4; j++) {                                          \
            const uint32_t _ad = (sb_) + b_warp                                \
                + (uint32_t)((j * 4 + (ks_)) * 256) + lane8;                   \
            asm volatile("ld.shared.v2.u32 {%0,%1}, [%2];"                     \
                : "=r"(bf[buf_][j][0]), "=r"(bf[buf_][j][1]) : "r"(_ad));      \
        }                                                                      \
    } while (0)

    #define LD_A(sa_, ks_, i_, buf_)                                           \
    do {                                                                       \
        const uint32_t _ad = (sa_) + a_warp                                    \
            + (uint32_t)(((i_) * 4 + (ks_)) * 512) + lane16;                   \
        asm volatile("ld.shared.v4.u32 {%0,%1,%2,%3}, [%4];"                   \
            : "=r"(af[buf_][0]), "=r"(af[buf_][1]),                            \
              "=r"(af[buf_][2]), "=r"(af[buf_][3]) : "r"(_ad));                \
    } while (0)

    for (int kt = 0; kt < NKT; kt++) {
        CP_WAIT(1);
        __syncthreads();

        const int kn = kt + 2;
        if (kn < NKT) ISSUE_STAGE(kn, s_nxt);
        CP_COMMIT();

        const uint32_t sa = sbase + (uint32_t)s_cur * STAGE_BYTES;
        const uint32_t sb = sa + A_ST_BYTES;

        // prime the register pipeline for this ktile
        LD_B(sb, 0, 0);
        LD_A(sa, 0, 0, 0);

        #pragma unroll
        for (int ks = 0; ks < 4; ks++) {
            #pragma unroll
            for (int i = 0; i < 4; i++) {
                const int cur = (ks * 4 + i) & 1;
                // prefetch next fragment(s) while current MMAs issue
                if (i < 3) {
                    LD_A(sa, ks, i + 1, cur ^ 1);
                } else if (ks < 3) {
                    LD_B(sb, ks + 1, (ks & 1) ^ 1);
                    LD_A(sa, ks + 1, 0, cur ^ 1);
                }
                #pragma unroll
                for (int j = 0; j < 4; j++)
                    MMA_F16(acc[i][j],
                            af[cur][0], af[cur][1], af[cur][2], af[cur][3],
                            bf[ks & 1][j][0], bf[ks & 1][j][1]);
            }
        }

        s_cur = (s_cur == 2) ? 0 : s_cur + 1;
        s_nxt = (s_nxt == 2) ? 0 : s_nxt + 1;
    }

    // ---- epilogue: scale and store ----
    const int orow0 = m0 + wm * 64;
    const int ocol0 = n0 + wn * 32;
    #pragma unroll
    for (int j = 0; j < 4; j++) {
        const int col = ocol0 + j * 8 + 2 * t;
        const float2 sc = *reinterpret_cast<const float2*>(scales + col);
        #pragma unroll
        for (int i = 0; i < 4; i++) {
            const int row = orow0 + i * 16 + g;
            float2 v0 = { acc[i][j][0] * sc.x, acc[i][j][1] * sc.y };
            float2 v1 = { acc[i][j][2] * sc.x, acc[i][j][3] * sc.y };
            *reinterpret_cast<float2*>(out + (size_t)row * NDIM + col)       = v0;
            *reinterpret_cast<float2*>(out + (size_t)(row + 8) * NDIM + col) = v1;
        }
    }
}

// ---------------- host ----------------
extern "C" void kernel_launch(void* const* d_in, const int* in_sizes, int n_in,
                              void* d_out, int out_size) {
    const float* input  = (const float*)d_in[0];
    const int*   weight = (const int*)d_in[1];
    const float* scales = (const float*)d_in[2];
    float* out = (float*)d_out;

    {
        dim3 ga(KDIM / 512, MDIM / 16);   // (8, 512)
        pack_a_kernel<<<ga, 256>>>(input);
        dim3 gw(KDIM / 512, NDIM / 8);    // (8, 512)
        pack_w_kernel<<<gw, 256>>>(weight);
    }

    cudaFuncSetAttribute(gemm_kernel,
                         cudaFuncAttributeMaxDynamicSharedMemorySize, SMEM_BYTES);
    const int grid = (MDIM / BM) * (NDIM / BN);   // 2048
    gemm_kernel<<<grid, 256, SMEM_BYTES>>>(scales, out);
}